// round 4
// baseline (speedup 1.0000x reference)
#include <cuda_runtime.h>
#include <math.h>

#define NN 131072
#define FN 64
#define FF 16
#define HH 128
#define EE 2097152
#define BB 256
#define LL 32
#define G4 512

// ---------------- scratch (device globals; no allocation) ----------------
__device__ int   g_deg[NN];
__device__ int   g_off[NN];
__device__ int   g_cur[NN];
__device__ int   g_bsum[128];
__device__ int   g_csr[EE];
__device__ float g_mean[NN*HH];     // layer1 uses stride 64, layer2 stride 128
__device__ float g_h1[NN*HH];
__device__ float g_emb[NN*HH];
__device__ float g_gsum[BB*HH];
__device__ int   g_bcnt[BB];
__device__ float g_Xg[BB*LL*G4];
__device__ float g_hst[BB*HH];

// ---------------- init ----------------
__global__ void k_zero(){
  int i = blockIdx.x*256 + threadIdx.x;
  if (i < NN) g_deg[i] = 0;
  if (i < BB) g_bcnt[i] = 0;
  if (i < BB*HH) g_gsum[i]=0.f;
}

// ---------------- CSR build ----------------
__global__ void k_degree(const int* __restrict__ ei){
  int e = blockIdx.x*256+threadIdx.x;
  if (e < EE) atomicAdd(&g_deg[ei[EE+e]], 1);
}

__global__ void k_scanA(){
  __shared__ int s[256];
  int tid=threadIdx.x;
  int base = blockIdx.x*1024 + tid*4;
  int t = g_deg[base]+g_deg[base+1]+g_deg[base+2]+g_deg[base+3];
  s[tid]=t; __syncthreads();
  for(int o=128;o>0;o>>=1){ if(tid<o) s[tid]+=s[tid+o]; __syncthreads(); }
  if(tid==0) g_bsum[blockIdx.x]=s[0];
}

__global__ void k_scanB(){
  __shared__ int s[128];
  int t=threadIdx.x;
  int v=g_bsum[t]; s[t]=v; __syncthreads();
  for(int o=1;o<128;o<<=1){
    int a = (t>=o)? s[t-o] : 0; __syncthreads();
    s[t]+=a; __syncthreads();
  }
  g_bsum[t]=s[t]-v;   // exclusive block base
}

__global__ void k_scanC(){
  __shared__ int s[256];
  int tid=threadIdx.x;
  int base = blockIdx.x*1024 + tid*4;
  int d0=g_deg[base],d1=g_deg[base+1],d2=g_deg[base+2],d3=g_deg[base+3];
  int tot=d0+d1+d2+d3;
  s[tid]=tot; __syncthreads();
  for(int o=1;o<256;o<<=1){
    int a=(tid>=o)? s[tid-o]:0; __syncthreads();
    s[tid]+=a; __syncthreads();
  }
  int run = g_bsum[blockIdx.x] + s[tid]-tot;
  g_off[base  ]=run; g_cur[base  ]=run; run+=d0;
  g_off[base+1]=run; g_cur[base+1]=run; run+=d1;
  g_off[base+2]=run; g_cur[base+2]=run; run+=d2;
  g_off[base+3]=run; g_cur[base+3]=run;
}

__global__ void k_csr(const int* __restrict__ ei){
  int e = blockIdx.x*256+threadIdx.x;
  if (e < EE){
    int src = ei[e], dst = ei[EE+e];
    int p = atomicAdd(&g_cur[dst],1);
    g_csr[p]=src;
  }
}

// ---------------- neighbor-mean gathers (warp per node) ----------------
__global__ void k_agg1(const float* __restrict__ x){
  int w = (blockIdx.x*256+threadIdx.x)>>5;
  int lane = threadIdx.x&31;
  if (w>=NN) return;
  int beg=g_off[w], d=g_deg[w];
  float ax=0.f, ay=0.f;
  for(int i=0;i<d;i++){
    int src=g_csr[beg+i];
    float2 v = *(const float2*)(x + (size_t)src*FN + lane*2);
    ax+=v.x; ay+=v.y;
  }
  float inv = 1.0f/(float)max(d,1);
  float2 o; o.x=ax*inv; o.y=ay*inv;
  *(float2*)(g_mean + (size_t)w*FN + lane*2) = o;
}

__global__ void k_agg2(){
  int w = (blockIdx.x*256+threadIdx.x)>>5;
  int lane=threadIdx.x&31;
  if (w>=NN) return;
  int beg=g_off[w], d=g_deg[w];
  float4 acc = {0.f,0.f,0.f,0.f};
  for(int i=0;i<d;i++){
    int src=g_csr[beg+i];
    float4 v=*(const float4*)(g_h1 + (size_t)src*HH + lane*4);
    acc.x+=v.x; acc.y+=v.y; acc.z+=v.z; acc.w+=v.w;
  }
  float inv=1.f/(float)max(d,1);
  acc.x*=inv; acc.y*=inv; acc.z*=inv; acc.w*=inv;
  *(float4*)(g_mean + (size_t)w*HH + lane*4) = acc;
}

// ---------------- tf32 tensor-core GEMM ----------------
// C = act([A1|A2] @ [W1|W2]^T + bias1 + bias2)
// BM=128, BN=64, BK=32. 256 threads = 8 warps in 4x2 (M,N) grid,
// each warp 32x32 via 2x4 tiles of mma.sync.m16n8k8.tf32.

__device__ __forceinline__ unsigned f2tf(float v){
  unsigned o; asm("cvt.rna.tf32.f32 %0, %1;" : "=r"(o) : "f"(v)); return o;
}

__device__ __forceinline__ void mma_tf32(float* c, const unsigned* a, unsigned b0, unsigned b1){
  asm volatile("mma.sync.aligned.m16n8k8.row.col.f32.tf32.tf32.f32 "
    "{%0,%1,%2,%3}, {%4,%5,%6,%7}, {%8,%9}, {%0,%1,%2,%3};"
    : "+f"(c[0]), "+f"(c[1]), "+f"(c[2]), "+f"(c[3])
    : "r"(a[0]), "r"(a[1]), "r"(a[2]), "r"(a[3]), "r"(b0), "r"(b1));
}

template<bool RELU, bool GATHER>
__global__ void __launch_bounds__(256) k_gemm_tc(
    const float* __restrict__ A1, int K1,
    const float* __restrict__ A2, int K2,
    const float* __restrict__ W1, const float* __restrict__ W2,
    const float* __restrict__ bias1, const float* __restrict__ bias2,
    const int* __restrict__ gidx,
    float* __restrict__ C, int OUT)
{
  __shared__ __align__(16) unsigned As[128][36];
  __shared__ __align__(16) unsigned Bs[64][36];   // Bs[n][k]
  int tid = threadIdx.x;
  int warp = tid>>5, lane = tid&31;
  int wm = warp & 3, wn = warp >> 2;     // M32-chunk, N32-chunk
  int m0 = blockIdx.x*128, j0 = blockIdx.y*64;
  int g = lane>>2, qq = lane&3;
  float acc[2][4][4];
  #pragma unroll
  for(int mt=0;mt<2;mt++)
    #pragma unroll
    for(int nt=0;nt<4;nt++)
      #pragma unroll
      for(int q=0;q<4;q++) acc[mt][nt][q]=0.f;

  int K = K1+K2;
  for(int k0=0;k0<K;k0+=32){
    bool inA1 = (k0 < K1);      // K1 is a multiple of 32 in all uses
    const float* Ab = inA1 ? A1 : A2;
    const float* Wb = inA1 ? W1 : W2;
    int kb  = inA1 ? k0 : (k0-K1);
    int Kst = inA1 ? K1 : K2;
    // load A chunk 128x32 (4 float4 per thread)
    #pragma unroll
    for(int p=0;p<4;p++){
      int u = tid + p*256;
      int row = u>>3, kq = (u&7)*4;
      int m = m0+row;
      int r = GATHER ? __ldg(&gidx[m]) : m;
      float4 v = *(const float4*)(Ab + (size_t)r*Kst + kb + kq);
      uint4 o; o.x=f2tf(v.x); o.y=f2tf(v.y); o.z=f2tf(v.z); o.w=f2tf(v.w);
      *(uint4*)&As[row][kq] = o;
    }
    // load W chunk 64x32 (2 float4 per thread)
    #pragma unroll
    for(int p=0;p<2;p++){
      int u = tid + p*256;
      int j = u>>3, kq = (u&7)*4;
      float4 w = *(const float4*)(Wb + (size_t)(j0+j)*Kst + kb + kq);
      uint4 o; o.x=f2tf(w.x); o.y=f2tf(w.y); o.z=f2tf(w.z); o.w=f2tf(w.w);
      *(uint4*)&Bs[j][kq] = o;
    }
    __syncthreads();
    #pragma unroll
    for(int ks=0;ks<4;ks++){
      int kc = ks*8 + qq;
      unsigned a[2][4];
      #pragma unroll
      for(int mt=0;mt<2;mt++){
        int r = wm*32 + mt*16 + g;
        a[mt][0]=As[r][kc];   a[mt][1]=As[r+8][kc];
        a[mt][2]=As[r][kc+4]; a[mt][3]=As[r+8][kc+4];
      }
      #pragma unroll
      for(int nt=0;nt<4;nt++){
        int nn = wn*32 + nt*8 + g;
        unsigned b0 = Bs[nn][kc], b1 = Bs[nn][kc+4];
        #pragma unroll
        for(int mt=0;mt<2;mt++)
          mma_tf32(acc[mt][nt], a[mt], b0, b1);
      }
    }
    __syncthreads();
  }
  // epilogue
  #pragma unroll
  for(int nt=0;nt<4;nt++){
    int col = j0 + wn*32 + nt*8 + qq*2;
    float bb0=0.f, bb1=0.f;
    if(bias1){ bb0=bias1[col]; bb1=bias1[col+1]; }
    if(bias2){ bb0+=bias2[col]; bb1+=bias2[col+1]; }
    #pragma unroll
    for(int mt=0;mt<2;mt++){
      int row = m0 + wm*32 + mt*16 + g;
      float2 v0, v1;
      v0.x=acc[mt][nt][0]+bb0; v0.y=acc[mt][nt][1]+bb1;
      v1.x=acc[mt][nt][2]+bb0; v1.y=acc[mt][nt][3]+bb1;
      if(RELU){
        v0.x=fmaxf(v0.x,0.f); v0.y=fmaxf(v0.y,0.f);
        v1.x=fmaxf(v1.x,0.f); v1.y=fmaxf(v1.y,0.f);
      }
      *(float2*)(C + (size_t)row*OUT + col)     = v0;
      *(float2*)(C + (size_t)(row+8)*OUT + col) = v1;
    }
  }
}

// ---------------- graph mean-pool (batch is sorted) ----------------
__global__ void k_gsum(const int* __restrict__ batch){
  int f=threadIdx.x;       // 128
  int n0=blockIdx.x*128;
  int cur=batch[n0];
  float acc=0.f; int rl=0;
  for(int i=0;i<128;i++){
    int n=n0+i;
    int bb=batch[n];
    if(bb!=cur){
      atomicAdd(&g_gsum[cur*HH+f], acc);
      if(f==0) atomicAdd(&g_bcnt[cur], rl);
      acc=0.f; rl=0; cur=bb;
    }
    acc += g_emb[(size_t)n*HH+f];
    rl++;
  }
  atomicAdd(&g_gsum[cur*HH+f], acc);
  if(f==0) atomicAdd(&g_bcnt[cur], rl);
}

// ---------------- fused LSTM: whole recurrence in one launch ----------------
// 64 blocks x 256 threads; block owns 4 batch rows; thread owns gate cols 2t,2t+1.
__device__ __forceinline__ float sigf(float v){ return 1.f/(1.f+expf(-v)); }

__global__ void __launch_bounds__(256) k_lstm_fused(const float* __restrict__ Whh,
                                                    const int* __restrict__ plen){
  __shared__ float hs[4][128];
  __shared__ float cs[4][128];
  __shared__ float Gs[4][512];
  __shared__ int lens[4];
  int tid=threadIdx.x;
  int r0=blockIdx.x*4;
  if(tid<4) lens[tid]=plen[r0+tid];
  for(int i=tid;i<512;i+=256){ ((float*)hs)[i]=0.f; ((float*)cs)[i]=0.f; }
  __syncthreads();
  int l0=lens[0], l1=lens[1], l2=lens[2], l3=lens[3];
  int maxlen = max(max(l0,l1),max(l2,l3));
  int j = tid*2;
  const float4* w0 = (const float4*)(Whh + (size_t)j*HH);
  const float4* w1 = (const float4*)(Whh + (size_t)(j+1)*HH);
  for(int t=0;t<maxlen;t++){
    float g0[4]={0.f,0.f,0.f,0.f}, g1[4]={0.f,0.f,0.f,0.f};
    bool a0=t<l0, a1=t<l1, a2=t<l2, a3=t<l3;
    #pragma unroll 1
    for(int kc=0;kc<32;kc+=8){
      float4 wa[8], wb[8];
      #pragma unroll
      for(int q=0;q<8;q++){ wa[q]=w0[kc+q]; wb[q]=w1[kc+q]; }
      #pragma unroll
      for(int rr=0;rr<4;rr++){
        bool act = (rr==0)?a0:(rr==1)?a1:(rr==2)?a2:a3;
        if(!act) continue;
        #pragma unroll
        for(int q=0;q<8;q++){
          float4 h4 = *(const float4*)&hs[rr][(kc+q)*4];
          g0[rr] += wa[q].x*h4.x + wa[q].y*h4.y + wa[q].z*h4.z + wa[q].w*h4.w;
          g1[rr] += wb[q].x*h4.x + wb[q].y*h4.y + wb[q].z*h4.z + wb[q].w*h4.w;
        }
      }
    }
    #pragma unroll
    for(int rr=0;rr<4;rr++){
      const float* xr = g_Xg + ((size_t)(r0+rr)*LL + t)*G4;
      float2 o; o.x = g0[rr] + xr[j]; o.y = g1[rr] + xr[j+1];
      *(float2*)&Gs[rr][j] = o;
    }
    __syncthreads();
    #pragma unroll
    for(int p=0;p<2;p++){
      int u = tid + p*256;
      int rr = u>>7, k = u&127;
      if(t < lens[rr]){
        float ig=Gs[rr][k], fg=Gs[rr][128+k], gg=Gs[rr][256+k], og=Gs[rr][384+k];
        float c = cs[rr][k];
        float cn = sigf(fg)*c + sigf(ig)*tanhf(gg);
        cs[rr][k]=cn;
        hs[rr][k]=sigf(og)*tanhf(cn);
      }
    }
    __syncthreads();
  }
  #pragma unroll
  for(int p=0;p<2;p++){
    int u = tid + p*256;
    int rr = u>>7, k = u&127;
    g_hst[(size_t)(r0+rr)*HH + k] = hs[rr][k];
  }
}

// ---------------- final: flow MLP + concat + scoring MLP ----------------
__global__ void k_combine(const float* __restrict__ flow, const float* __restrict__ Wf,
   const float* __restrict__ bf, const float* __restrict__ Ws1, const float* __restrict__ bs1,
   const float* __restrict__ Ws2, const float* __restrict__ bs2, float* __restrict__ out)
{
  __shared__ __align__(16) float comb[320];
  __shared__ float red[128];
  int b=blockIdx.x, tid=threadIdx.x;   // 128 threads
  float cnt=(float)max(g_bcnt[b],1);
  comb[tid]      = g_gsum[b*HH+tid]/cnt;
  comb[128+tid]  = g_hst[b*HH+tid];
  if(tid<64){
    float a=bf[tid];
    #pragma unroll
    for(int i=0;i<16;i++) a += flow[b*FF+i]*Wf[tid*FF+i];
    comb[256+tid]=fmaxf(a,0.f);
  }
  __syncthreads();
  float s=bs1[tid];
  const float4* w4=(const float4*)(Ws1 + (size_t)tid*320);
  const float4* c4=(const float4*)comb;
  #pragma unroll 8
  for(int k=0;k<80;k++){
    float4 w=w4[k], c=c4[k];
    s += w.x*c.x + w.y*c.y + w.z*c.z + w.w*c.w;
  }
  s=fmaxf(s,0.f);
  red[tid]=s*Ws2[tid];
  __syncthreads();
  for(int o=64;o>0;o>>=1){ if(tid<o) red[tid]+=red[tid+o]; __syncthreads(); }
  if(tid==0) out[b]=red[0]+bs2[0];
}

// ---------------- launch ----------------
extern "C" void kernel_launch(void* const* d_in, const int* in_sizes, int n_in,
                              void* d_out, int out_size){
  const float* x   =(const float*)d_in[0];
  const int*   ei  =(const int*)  d_in[1];
  const int*   batch=(const int*) d_in[2];
  const int*   pidx=(const int*)  d_in[3];
  const int*   plen=(const int*)  d_in[4];
  const float* flow=(const float*)d_in[5];
  const float* Wl1=(const float*)d_in[6];
  const float* Wr1=(const float*)d_in[7];
  const float* b1 =(const float*)d_in[8];
  const float* Wl2=(const float*)d_in[9];
  const float* Wr2=(const float*)d_in[10];
  const float* b2 =(const float*)d_in[11];
  const float* Wih=(const float*)d_in[12];
  const float* Whh=(const float*)d_in[13];
  const float* bih=(const float*)d_in[14];
  const float* bhh=(const float*)d_in[15];
  const float* Wf =(const float*)d_in[16];
  const float* bf =(const float*)d_in[17];
  const float* Ws1=(const float*)d_in[18];
  const float* bs1=(const float*)d_in[19];
  const float* Ws2=(const float*)d_in[20];
  const float* bs2=(const float*)d_in[21];
  float* out=(float*)d_out;

  float *p_mean,*p_h1,*p_emb,*p_xg;
  cudaGetSymbolAddress((void**)&p_mean, g_mean);
  cudaGetSymbolAddress((void**)&p_h1,   g_h1);
  cudaGetSymbolAddress((void**)&p_emb,  g_emb);
  cudaGetSymbolAddress((void**)&p_xg,   g_Xg);

  k_zero<<<NN/256,256>>>();
  k_degree<<<EE/256,256>>>(ei);
  k_scanA<<<128,256>>>();
  k_scanB<<<1,128>>>();
  k_scanC<<<128,256>>>();
  k_csr<<<EE/256,256>>>(ei);

  // SAGE layer 1: h1 = relu(mean@Wl1^T + b1 + x@Wr1^T)
  k_agg1<<<NN/8,256>>>(x);
  k_gemm_tc<true,false><<<dim3(NN/128,2),256>>>(p_mean,FN, x,FN, Wl1,Wr1, b1,nullptr, nullptr, p_h1, HH);

  // SAGE layer 2
  k_agg2<<<NN/8,256>>>();
  k_gemm_tc<true,false><<<dim3(NN/128,2),256>>>(p_mean,HH, p_h1,HH, Wl2,Wr2, b2,nullptr, nullptr, p_emb, HH);

  // graph pooling
  k_gsum<<<NN/128,128>>>(batch);

  // LSTM input precompute: Xg[b,t,:] = node_emb[path_idx] @ Wih^T + bih + bhh
  k_gemm_tc<false,true><<<dim3(BB*LL/128,8),256>>>(p_emb,HH, nullptr,0, Wih,nullptr, bih,bhh, pidx, p_xg, G4);

  // LSTM recurrence (single fused launch)
  k_lstm_fused<<<BB/4,256>>>(Whh, plen);

  // final scoring
  k_combine<<<BB,128>>>(flow,Wf,bf,Ws1,bs1,Ws2,bs2,out);
}

// round 6
// speedup vs baseline: 1.6113x; 1.6113x over previous
#include <cuda_runtime.h>
#include <math.h>

#define NN 131072
#define FN 64
#define FF 16
#define HH 128
#define EE 2097152
#define BB 256
#define LL 32
#define G4 512

// ---------------- scratch (device globals; no allocation) ----------------
__device__ int   g_deg[NN];
__device__ int   g_off[NN];
__device__ int   g_cur[NN];
__device__ int   g_bsum[128];
__device__ int   g_csr[EE];
__device__ float g_mean[NN*HH];     // layer1 uses stride 64, layer2 stride 128
__device__ float g_h1[NN*HH];
__device__ float g_emb[NN*HH];
__device__ float g_gsum[BB*HH];
__device__ int   g_bcnt[BB];
__device__ float g_Xg[BB*LL*G4];
__device__ float g_hst[BB*HH];

// ---------------- f32x2 packed helpers ----------------
__device__ __forceinline__ void fma2(unsigned long long &d, unsigned long long a, unsigned long long b){
  asm("fma.rn.f32x2 %0, %1, %2, %0;" : "+l"(d) : "l"(a), "l"(b));
}
__device__ __forceinline__ unsigned long long dup2(float a){
  unsigned long long r; asm("mov.b64 %0, {%1, %1};" : "=l"(r) : "f"(a)); return r;
}
__device__ __forceinline__ void unp2(unsigned long long v, float &lo, float &hi){
  asm("mov.b64 {%0, %1}, %2;" : "=f"(lo), "=f"(hi) : "l"(v));
}

// ---------------- init ----------------
__global__ void k_zero(){
  int i = blockIdx.x*256 + threadIdx.x;
  if (i < NN) g_deg[i] = 0;
  if (i < BB) g_bcnt[i] = 0;
  if (i < BB*HH) g_gsum[i]=0.f;
}

// ---------------- CSR build ----------------
__global__ void k_degree(const int* __restrict__ ei){
  int e = blockIdx.x*256+threadIdx.x;
  if (e < EE) atomicAdd(&g_deg[ei[EE+e]], 1);
}

__global__ void k_scanA(){
  __shared__ int s[256];
  int tid=threadIdx.x;
  int base = blockIdx.x*1024 + tid*4;
  int t = g_deg[base]+g_deg[base+1]+g_deg[base+2]+g_deg[base+3];
  s[tid]=t; __syncthreads();
  for(int o=128;o>0;o>>=1){ if(tid<o) s[tid]+=s[tid+o]; __syncthreads(); }
  if(tid==0) g_bsum[blockIdx.x]=s[0];
}

__global__ void k_scanB(){
  __shared__ int s[128];
  int t=threadIdx.x;
  int v=g_bsum[t]; s[t]=v; __syncthreads();
  for(int o=1;o<128;o<<=1){
    int a = (t>=o)? s[t-o] : 0; __syncthreads();
    s[t]+=a; __syncthreads();
  }
  g_bsum[t]=s[t]-v;   // exclusive block base
}

__global__ void k_scanC(){
  __shared__ int s[256];
  int tid=threadIdx.x;
  int base = blockIdx.x*1024 + tid*4;
  int d0=g_deg[base],d1=g_deg[base+1],d2=g_deg[base+2],d3=g_deg[base+3];
  int tot=d0+d1+d2+d3;
  s[tid]=tot; __syncthreads();
  for(int o=1;o<256;o<<=1){
    int a=(tid>=o)? s[tid-o]:0; __syncthreads();
    s[tid]+=a; __syncthreads();
  }
  int run = g_bsum[blockIdx.x] + s[tid]-tot;
  g_off[base  ]=run; g_cur[base  ]=run; run+=d0;
  g_off[base+1]=run; g_cur[base+1]=run; run+=d1;
  g_off[base+2]=run; g_cur[base+2]=run; run+=d2;
  g_off[base+3]=run; g_cur[base+3]=run;
}

__global__ void k_csr(const int* __restrict__ ei){
  int e = blockIdx.x*256+threadIdx.x;
  if (e < EE){
    int src = ei[e], dst = ei[EE+e];
    int p = atomicAdd(&g_cur[dst],1);
    g_csr[p]=src;
  }
}

// ---------------- neighbor-mean gathers (warp per node) ----------------
__global__ void k_agg1(const float* __restrict__ x){
  int w = (blockIdx.x*256+threadIdx.x)>>5;
  int lane = threadIdx.x&31;
  if (w>=NN) return;
  int beg=g_off[w], d=g_deg[w];
  float ax=0.f, ay=0.f;
  for(int i=0;i<d;i++){
    int src=g_csr[beg+i];
    float2 v = *(const float2*)(x + (size_t)src*FN + lane*2);
    ax+=v.x; ay+=v.y;
  }
  float inv = 1.0f/(float)max(d,1);
  float2 o; o.x=ax*inv; o.y=ay*inv;
  *(float2*)(g_mean + (size_t)w*FN + lane*2) = o;
}

__global__ void k_agg2(){
  int w = (blockIdx.x*256+threadIdx.x)>>5;
  int lane=threadIdx.x&31;
  if (w>=NN) return;
  int beg=g_off[w], d=g_deg[w];
  float4 acc = {0.f,0.f,0.f,0.f};
  for(int i=0;i<d;i++){
    int src=g_csr[beg+i];
    float4 v=*(const float4*)(g_h1 + (size_t)src*HH + lane*4);
    acc.x+=v.x; acc.y+=v.y; acc.z+=v.z; acc.w+=v.w;
  }
  float inv=1.f/(float)max(d,1);
  acc.x*=inv; acc.y*=inv; acc.z*=inv; acc.w*=inv;
  *(float4*)(g_mean + (size_t)w*HH + lane*4) = acc;
}

// ---------------- f32x2 SGEMM: C = act([A1|A2] @ [W1|W2]^T + bias1 + bias2) ----------------
// BM=128, BN=128, BK=16, 256 threads, 8x8 microtile as 8x4 f32x2 pairs.
template<bool RELU, bool GATHER>
__global__ void __launch_bounds__(256,2) k_gemm_f2(
    const float* __restrict__ A1, int K1,
    const float* __restrict__ A2, int K2,
    const float* __restrict__ W1, const float* __restrict__ W2,
    const float* __restrict__ bias1, const float* __restrict__ bias2,
    const int* __restrict__ gidx,
    float* __restrict__ C, int OUT)
{
  __shared__ __align__(16) float As[128][20];
  __shared__ __align__(16) float Ws[16][140];
  int tid=threadIdx.x;
  int m0=blockIdx.x*128, j0=blockIdx.y*128;
  int ty=tid>>4, tx=tid&15;
  unsigned long long acc[8][4];
  #pragma unroll
  for(int i=0;i<8;i++)
    #pragma unroll
    for(int q=0;q<4;q++) acc[i][q]=0ULL;

  int K=K1+K2;
  for(int k0=0;k0<K;k0+=16){
    bool inA1 = (k0 < K1);   // K1 multiple of 16 in all uses
    const float* Ab = inA1 ? A1 : A2;
    const float* Wb = inA1 ? W1 : W2;
    int kb  = inA1 ? k0 : (k0-K1);
    int Kst = inA1 ? K1 : K2;
    // A tile 128x16 : 512 float4, 2 per thread
    #pragma unroll
    for(int p=0;p<2;p++){
      int u=tid+p*256;
      int mm=u>>2, kq=(u&3)*4;
      int m=m0+mm;
      int r = GATHER ? __ldg(&gidx[m]) : m;
      float4 v = *(const float4*)(Ab + (size_t)r*Kst + kb + kq);
      *(float4*)&As[mm][kq] = v;
    }
    // W tile 128x16 -> transposed store Ws[k][j]
    #pragma unroll
    for(int p=0;p<2;p++){
      int u=tid+p*256;
      int jj=u>>2, kq=(u&3)*4;
      float4 w = *(const float4*)(Wb + (size_t)(j0+jj)*Kst + kb + kq);
      Ws[kq+0][jj]=w.x; Ws[kq+1][jj]=w.y; Ws[kq+2][jj]=w.z; Ws[kq+3][jj]=w.w;
    }
    __syncthreads();
    #pragma unroll
    for(int kk=0;kk<16;kk++){
      ulonglong2 b01 = *(const ulonglong2*)&Ws[kk][tx*8];
      ulonglong2 b23 = *(const ulonglong2*)&Ws[kk][tx*8+4];
      #pragma unroll
      for(int i=0;i<8;i++){
        unsigned long long a2 = dup2(As[ty*8+i][kk]);
        fma2(acc[i][0], a2, b01.x);
        fma2(acc[i][1], a2, b01.y);
        fma2(acc[i][2], a2, b23.x);
        fma2(acc[i][3], a2, b23.y);
      }
    }
    __syncthreads();
  }
  // epilogue
  int j=j0+tx*8;
  float bb[8];
  #pragma unroll
  for(int q=0;q<8;q++){
    float v = bias1 ? bias1[j+q] : 0.f;
    if(bias2) v += bias2[j+q];
    bb[q]=v;
  }
  #pragma unroll
  for(int i=0;i<8;i++){
    int m=m0+ty*8+i;
    float o[8];
    #pragma unroll
    for(int q=0;q<4;q++){
      float lo,hi; unp2(acc[i][q], lo, hi);
      o[q*2]=lo+bb[q*2]; o[q*2+1]=hi+bb[q*2+1];
    }
    if(RELU){
      #pragma unroll
      for(int q=0;q<8;q++) o[q]=fmaxf(o[q],0.f);
    }
    float4 v0; v0.x=o[0]; v0.y=o[1]; v0.z=o[2]; v0.w=o[3];
    float4 v1; v1.x=o[4]; v1.y=o[5]; v1.z=o[6]; v1.w=o[7];
    *(float4*)(C + (size_t)m*OUT + j)     = v0;
    *(float4*)(C + (size_t)m*OUT + j + 4) = v1;
  }
}

// ---------------- graph mean-pool (batch is sorted) ----------------
__global__ void k_gsum(const int* __restrict__ batch){
  int f=threadIdx.x;       // 128
  int n0=blockIdx.x*128;
  int cur=batch[n0];
  float acc=0.f; int rl=0;
  for(int i=0;i<128;i++){
    int n=n0+i;
    int bb=batch[n];
    if(bb!=cur){
      atomicAdd(&g_gsum[cur*HH+f], acc);
      if(f==0) atomicAdd(&g_bcnt[cur], rl);
      acc=0.f; rl=0; cur=bb;
    }
    acc += g_emb[(size_t)n*HH+f];
    rl++;
  }
  atomicAdd(&g_gsum[cur*HH+f], acc);
  if(f==0) atomicAdd(&g_bcnt[cur], rl);
}

// ---------------- LSTM: cluster-of-2, Whh register-resident ----------------
// 128 clusters x 2 CTAs x 256 threads. Cluster handles 2 batch rows.
// CTA rank r owns gate cols [r*256, r*256+256). Each thread keeps its Whh row
// (128 floats) in registers for the whole recurrence. Gate halves exchanged
// via DSMEM (double-buffered, one cluster.sync per step).
__device__ __forceinline__ float sigf(float v){ return 1.f/(1.f+expf(-v)); }

__device__ __forceinline__ unsigned smem_u32(const void* p){
  unsigned a; asm("{ .reg .u64 t; cvta.to.shared.u64 t, %1; cvt.u32.u64 %0, t; }" : "=r"(a) : "l"(p));
  return a;
}
__device__ __forceinline__ unsigned mapa_u32(unsigned a, unsigned r){
  unsigned o; asm("mapa.shared::cluster.u32 %0, %1, %2;" : "=r"(o) : "r"(a), "r"(r));
  return o;
}
__device__ __forceinline__ void st_cl(unsigned a, float v){
  asm volatile("st.shared::cluster.f32 [%0], %1;" :: "r"(a), "f"(v));
}
#define CLSYNC() do{ asm volatile("barrier.cluster.arrive.aligned;":::"memory"); \
                     asm volatile("barrier.cluster.wait.aligned;":::"memory"); }while(0)

__global__ void __launch_bounds__(256,1) __cluster_dims__(2,1,1)
k_lstm_cl(const float* __restrict__ Whh, const int* __restrict__ plen){
  __shared__ __align__(16) float hs[2][128];
  __shared__ __align__(16) float cs[2][128];
  __shared__ __align__(16) float Gb[2][2][512];  // [buf][row][gatecol]
  __shared__ int lens[2];
  int tid=threadIdx.x;
  unsigned rank; asm("mov.u32 %0, %%cluster_ctarank;" : "=r"(rank));
  int pair = blockIdx.x>>1;
  int r0 = pair*2;
  int gc = rank*256 + tid;      // global gate column 0..511

  if(tid<2) lens[tid]=plen[r0+tid];
  if(tid<256){ hs[0][tid&127]=0.f; cs[0][tid&127]=0.f; }
  if(tid<256){ hs[1][tid&127]=0.f; cs[1][tid&127]=0.f; }

  // load Whh row gc into registers (64 f32x2 pairs)
  ulonglong2 w[32];
  const ulonglong2* wr = (const ulonglong2*)(Whh + (size_t)gc*HH);
  #pragma unroll
  for(int q=0;q<32;q++) w[q]=wr[q];

  unsigned gbase = smem_u32(&Gb[0][0][0]);
  unsigned peer = rank^1u;
  __syncthreads();
  CLSYNC();

  int l0=lens[0], l1=lens[1];
  int maxlen = max(l0,l1);
  const float* x0 = g_Xg + ((size_t)r0*LL)*G4 + gc;
  const float* x1 = g_Xg + ((size_t)(r0+1)*LL)*G4 + gc;

  for(int t=0;t<maxlen;t++){
    // gates for both rows, this thread's column
    unsigned long long a0=0ULL, b0=0ULL, a1=0ULL, b1=0ULL;
    #pragma unroll
    for(int q=0;q<32;q+=2){
      ulonglong2 h0a = *(const ulonglong2*)&hs[0][q*4];
      ulonglong2 h0b = *(const ulonglong2*)&hs[0][q*4+4];
      ulonglong2 h1a = *(const ulonglong2*)&hs[1][q*4];
      ulonglong2 h1b = *(const ulonglong2*)&hs[1][q*4+4];
      fma2(a0, w[q].x,   h0a.x); fma2(b0, w[q].y,   h0a.y);
      fma2(a0, w[q+1].x, h0b.x); fma2(b0, w[q+1].y, h0b.y);
      fma2(a1, w[q].x,   h1a.x); fma2(b1, w[q].y,   h1a.y);
      fma2(a1, w[q+1].x, h1b.x); fma2(b1, w[q+1].y, h1b.y);
    }
    float e,oo,e2,o2;
    unp2(a0,e,oo); unp2(b0,e2,o2);
    float g0 = e+oo+e2+o2 + x0[t*G4];
    unp2(a1,e,oo); unp2(b1,e2,o2);
    float g1 = e+oo+e2+o2 + x1[t*G4];

    int buf = t&1;
    Gb[buf][0][gc]=g0; Gb[buf][1][gc]=g1;
    unsigned off0 = gbase + (unsigned)(((buf*2+0)*512 + gc)*4);
    unsigned off1 = gbase + (unsigned)(((buf*2+1)*512 + gc)*4);
    st_cl(mapa_u32(off0, peer), g0);
    st_cl(mapa_u32(off1, peer), g1);
    CLSYNC();

    if(tid<256){
      int rr=tid>>7, k=tid&127;
      if(t < lens[rr]){
        float ig=Gb[buf][rr][k],     fg=Gb[buf][rr][128+k];
        float gg=Gb[buf][rr][256+k], og=Gb[buf][rr][384+k];
        float c = cs[rr][k];
        float cn = sigf(fg)*c + sigf(ig)*tanhf(gg);
        cs[rr][k]=cn;
        hs[rr][k]=sigf(og)*tanhf(cn);
      }
    }
    __syncthreads();
  }
  if(tid<256){
    int rr=tid>>7, k=tid&127;
    g_hst[(size_t)(r0+rr)*HH + k] = hs[rr][k];
  }
  CLSYNC();
}

// ---------------- final: flow MLP + concat + scoring MLP ----------------
__global__ void k_combine(const float* __restrict__ flow, const float* __restrict__ Wf,
   const float* __restrict__ bf, const float* __restrict__ Ws1, const float* __restrict__ bs1,
   const float* __restrict__ Ws2, const float* __restrict__ bs2, float* __restrict__ out)
{
  __shared__ __align__(16) float comb[320];
  __shared__ float red[128];
  int b=blockIdx.x, tid=threadIdx.x;   // 128 threads
  float cnt=(float)max(g_bcnt[b],1);
  comb[tid]      = g_gsum[b*HH+tid]/cnt;
  comb[128+tid]  = g_hst[b*HH+tid];
  if(tid<64){
    float a=bf[tid];
    #pragma unroll
    for(int i=0;i<16;i++) a += flow[b*FF+i]*Wf[tid*FF+i];
    comb[256+tid]=fmaxf(a,0.f);
  }
  __syncthreads();
  float s=bs1[tid];
  const float4* w4=(const float4*)(Ws1 + (size_t)tid*320);
  const float4* c4=(const float4*)comb;
  #pragma unroll 8
  for(int k=0;k<80;k++){
    float4 w=w4[k], c=c4[k];
    s += w.x*c.x + w.y*c.y + w.z*c.z + w.w*c.w;
  }
  s=fmaxf(s,0.f);
  red[tid]=s*Ws2[tid];
  __syncthreads();
  for(int o=64;o>0;o>>=1){ if(tid<o) red[tid]+=red[tid+o]; __syncthreads(); }
  if(tid==0) out[b]=red[0]+bs2[0];
}

// ---------------- launch ----------------
extern "C" void kernel_launch(void* const* d_in, const int* in_sizes, int n_in,
                              void* d_out, int out_size){
  const float* x   =(const float*)d_in[0];
  const int*   ei  =(const int*)  d_in[1];
  const int*   batch=(const int*) d_in[2];
  const int*   pidx=(const int*)  d_in[3];
  const int*   plen=(const int*)  d_in[4];
  const float* flow=(const float*)d_in[5];
  const float* Wl1=(const float*)d_in[6];
  const float* Wr1=(const float*)d_in[7];
  const float* b1 =(const float*)d_in[8];
  const float* Wl2=(const float*)d_in[9];
  const float* Wr2=(const float*)d_in[10];
  const float* b2 =(const float*)d_in[11];
  const float* Wih=(const float*)d_in[12];
  const float* Whh=(const float*)d_in[13];
  const float* bih=(const float*)d_in[14];
  const float* bhh=(const float*)d_in[15];
  const float* Wf =(const float*)d_in[16];
  const float* bf =(const float*)d_in[17];
  const float* Ws1=(const float*)d_in[18];
  const float* bs1=(const float*)d_in[19];
  const float* Ws2=(const float*)d_in[20];
  const float* bs2=(const float*)d_in[21];
  float* out=(float*)d_out;

  float *p_mean,*p_h1,*p_emb,*p_xg;
  cudaGetSymbolAddress((void**)&p_mean, g_mean);
  cudaGetSymbolAddress((void**)&p_h1,   g_h1);
  cudaGetSymbolAddress((void**)&p_emb,  g_emb);
  cudaGetSymbolAddress((void**)&p_xg,   g_Xg);

  k_zero<<<NN/256,256>>>();
  k_degree<<<EE/256,256>>>(ei);
  k_scanA<<<128,256>>>();
  k_scanB<<<1,128>>>();
  k_scanC<<<128,256>>>();
  k_csr<<<EE/256,256>>>(ei);

  // SAGE layer 1: h1 = relu(mean@Wl1^T + b1 + x@Wr1^T)
  k_agg1<<<NN/8,256>>>(x);
  k_gemm_f2<true,false><<<dim3(NN/128,1),256>>>(p_mean,FN, x,FN, Wl1,Wr1, b1,nullptr, nullptr, p_h1, HH);

  // SAGE layer 2
  k_agg2<<<NN/8,256>>>();
  k_gemm_f2<true,false><<<dim3(NN/128,1),256>>>(p_mean,HH, p_h1,HH, Wl2,Wr2, b2,nullptr, nullptr, p_emb, HH);

  // graph pooling
  k_gsum<<<NN/128,128>>>(batch);

  // LSTM input precompute: Xg[b,t,:] = node_emb[path_idx] @ Wih^T + bih + bhh
  k_gemm_f2<false,true><<<dim3(BB*LL/128,4),256>>>(p_emb,HH, nullptr,0, Wih,nullptr, bih,bhh, pidx, p_xg, G4);

  // LSTM recurrence (cluster kernel, Whh in registers)
  k_lstm_cl<<<BB,256>>>(Whh, plen);

  // final scoring
  k_combine<<<BB,128>>>(flow,Wf,bf,Ws1,bs1,Ws2,bs2,out);
}

// round 8
// speedup vs baseline: 1.6567x; 1.0282x over previous
#include <cuda_runtime.h>
#include <math.h>

#define NN 131072
#define FN 64
#define FF 16
#define HH 128
#define EE 2097152
#define BB 256
#define LL 32
#define G4 512

// ---------------- scratch (device globals; no allocation) ----------------
__device__ int   g_deg[NN];
__device__ int   g_off[NN];
__device__ int   g_cur[NN];
__device__ int   g_bsum[128];
__device__ int   g_csr[EE];
__device__ float g_mean[NN*HH];     // layer1 uses stride 64, layer2 stride 128
__device__ float g_h1[NN*HH];
__device__ float g_emb[NN*HH];
__device__ float g_gsum[BB*HH];
__device__ int   g_bcnt[BB];
__device__ float g_Xg[BB*LL*G4];
__device__ float g_hst[BB*HH];

// ---------------- f32x2 packed helpers ----------------
__device__ __forceinline__ void fma2(unsigned long long &d, unsigned long long a, unsigned long long b){
  asm("fma.rn.f32x2 %0, %1, %2, %0;" : "+l"(d) : "l"(a), "l"(b));
}
__device__ __forceinline__ unsigned long long dup2(float a){
  unsigned long long r; asm("mov.b64 %0, {%1, %1};" : "=l"(r) : "f"(a)); return r;
}
__device__ __forceinline__ void unp2(unsigned long long v, float &lo, float &hi){
  asm("mov.b64 {%0, %1}, %2;" : "=f"(lo), "=f"(hi) : "l"(v));
}
__device__ __forceinline__ unsigned smem_u32(const void* p){
  unsigned a; asm("{ .reg .u64 t; cvta.to.shared.u64 t, %1; cvt.u32.u64 %0, t; }" : "=r"(a) : "l"(p));
  return a;
}

// ---------------- init ----------------
__global__ void k_zero(){
  int i = blockIdx.x*256 + threadIdx.x;
  if (i < NN) g_deg[i] = 0;
  if (i < BB) g_bcnt[i] = 0;
  if (i < BB*HH) g_gsum[i]=0.f;
}

// ---------------- CSR build ----------------
__global__ void k_degree(const int* __restrict__ ei){
  int e = blockIdx.x*256+threadIdx.x;
  if (e < EE) atomicAdd(&g_deg[ei[EE+e]], 1);
}

__global__ void k_scanA(){
  __shared__ int s[256];
  int tid=threadIdx.x;
  int base = blockIdx.x*1024 + tid*4;
  int t = g_deg[base]+g_deg[base+1]+g_deg[base+2]+g_deg[base+3];
  s[tid]=t; __syncthreads();
  for(int o=128;o>0;o>>=1){ if(tid<o) s[tid]+=s[tid+o]; __syncthreads(); }
  if(tid==0) g_bsum[blockIdx.x]=s[0];
}

__global__ void k_scanB(){
  __shared__ int s[128];
  int t=threadIdx.x;
  int v=g_bsum[t]; s[t]=v; __syncthreads();
  for(int o=1;o<128;o<<=1){
    int a = (t>=o)? s[t-o] : 0; __syncthreads();
    s[t]+=a; __syncthreads();
  }
  g_bsum[t]=s[t]-v;   // exclusive block base
}

__global__ void k_scanC(){
  __shared__ int s[256];
  int tid=threadIdx.x;
  int base = blockIdx.x*1024 + tid*4;
  int d0=g_deg[base],d1=g_deg[base+1],d2=g_deg[base+2],d3=g_deg[base+3];
  int tot=d0+d1+d2+d3;
  s[tid]=tot; __syncthreads();
  for(int o=1;o<256;o<<=1){
    int a=(tid>=o)? s[tid-o]:0; __syncthreads();
    s[tid]+=a; __syncthreads();
  }
  int run = g_bsum[blockIdx.x] + s[tid]-tot;
  g_off[base  ]=run; g_cur[base  ]=run; run+=d0;
  g_off[base+1]=run; g_cur[base+1]=run; run+=d1;
  g_off[base+2]=run; g_cur[base+2]=run; run+=d2;
  g_off[base+3]=run; g_cur[base+3]=run;
}

__global__ void k_csr(const int* __restrict__ ei){
  int e = blockIdx.x*256+threadIdx.x;
  if (e < EE){
    int src = ei[e], dst = ei[EE+e];
    int p = atomicAdd(&g_cur[dst],1);
    g_csr[p]=src;
  }
}

// ---------------- neighbor-mean gathers (warp per node) ----------------
__global__ void k_agg1(const float* __restrict__ x){
  int w = (blockIdx.x*256+threadIdx.x)>>5;
  int lane = threadIdx.x&31;
  if (w>=NN) return;
  int beg=g_off[w], d=g_deg[w];
  float ax=0.f, ay=0.f;
  for(int i=0;i<d;i++){
    int src=g_csr[beg+i];
    float2 v = *(const float2*)(x + (size_t)src*FN + lane*2);
    ax+=v.x; ay+=v.y;
  }
  float inv = 1.0f/(float)max(d,1);
  float2 o; o.x=ax*inv; o.y=ay*inv;
  *(float2*)(g_mean + (size_t)w*FN + lane*2) = o;
}

__global__ void k_agg2(){
  int w = (blockIdx.x*256+threadIdx.x)>>5;
  int lane=threadIdx.x&31;
  if (w>=NN) return;
  int beg=g_off[w], d=g_deg[w];
  float4 acc = {0.f,0.f,0.f,0.f};
  for(int i=0;i<d;i++){
    int src=g_csr[beg+i];
    float4 v=*(const float4*)(g_h1 + (size_t)src*HH + lane*4);
    acc.x+=v.x; acc.y+=v.y; acc.z+=v.z; acc.w+=v.w;
  }
  float inv=1.f/(float)max(d,1);
  acc.x*=inv; acc.y*=inv; acc.z*=inv; acc.w*=inv;
  *(float4*)(g_mean + (size_t)w*HH + lane*4) = acc;
}

// ---------------- f32x2 SGEMM, double-buffered, transposed smem ----------------
// C = act([A1|A2] @ [W1|W2]^T + bias1 + bias2)
// BM=128, BN=128, BK=16, 256 threads, 8x8 microtile as 8x4 f32x2 pairs.
// As/Ws stored k-major [k][m]/[k][n], pad 136 floats (16B-aligned rows).
template<bool RELU, bool GATHER>
__global__ void __launch_bounds__(256,2) k_gemm_f2(
    const float* __restrict__ A1, int K1,
    const float* __restrict__ A2, int K2,
    const float* __restrict__ W1, const float* __restrict__ W2,
    const float* __restrict__ bias1, const float* __restrict__ bias2,
    const int* __restrict__ gidx,
    float* __restrict__ C, int OUT)
{
  __shared__ __align__(16) float As[2][16][136];
  __shared__ __align__(16) float Ws[2][16][136];
  int tid=threadIdx.x;
  int m0=blockIdx.x*128, j0=blockIdx.y*128;
  int ty=tid>>4, tx=tid&15;
  unsigned long long acc[8][4];
  #pragma unroll
  for(int i=0;i<8;i++)
    #pragma unroll
    for(int q=0;q<4;q++) acc[i][q]=0ULL;

  // per-thread loader coordinates: 2 float4 for A, 2 for W
  int lr0 = tid>>2,        lk0 = (tid&3)*4;        // u=tid
  int lr1 = (tid+256)>>2,  lk1 = (tid&3)*4;        // u=tid+256
  int arow0 = GATHER ? __ldg(&gidx[m0+lr0]) : (m0+lr0);
  int arow1 = GATHER ? __ldg(&gidx[m0+lr1]) : (m0+lr1);

  int NC1 = K1/16, NC = (K1+K2)/16;

  // chunk fetch -> regs
  float4 va0,va1,vw0,vw1;
  {
    const float* Ab = A1; const float* Wb = W1; int Kst = K1; int koff = 0;
    va0 = *(const float4*)(Ab + (size_t)arow0*Kst + koff + lk0);
    va1 = *(const float4*)(Ab + (size_t)arow1*Kst + koff + lk1);
    vw0 = *(const float4*)(Wb + (size_t)(j0+lr0)*Kst + koff + lk0);
    vw1 = *(const float4*)(Wb + (size_t)(j0+lr1)*Kst + koff + lk1);
  }
  // store chunk 0 -> buf 0
  #pragma unroll
  for(int j=0;j<4;j++){
    As[0][lk0+j][lr0] = ((const float*)&va0)[j];
    As[0][lk1+j][lr1] = ((const float*)&va1)[j];
    Ws[0][lk0+j][lr0] = ((const float*)&vw0)[j];
    Ws[0][lk1+j][lr1] = ((const float*)&vw1)[j];
  }
  __syncthreads();

  for(int c=0;c<NC;c++){
    int b = c&1;
    // prefetch chunk c+1
    if(c+1 < NC){
      bool in1 = (c+1 < NC1);
      const float* Ab = in1 ? A1 : A2;
      const float* Wb = in1 ? W1 : W2;
      int Kst  = in1 ? K1 : K2;
      int koff = (in1 ? (c+1) : (c+1-NC1))*16;
      va0 = *(const float4*)(Ab + (size_t)arow0*Kst + koff + lk0);
      va1 = *(const float4*)(Ab + (size_t)arow1*Kst + koff + lk1);
      vw0 = *(const float4*)(Wb + (size_t)(j0+lr0)*Kst + koff + lk0);
      vw1 = *(const float4*)(Wb + (size_t)(j0+lr1)*Kst + koff + lk1);
    }
    // compute from buf b
    #pragma unroll
    for(int kk=0;kk<16;kk++){
      float4 a01 = *(const float4*)&As[b][kk][ty*8];
      float4 a23 = *(const float4*)&As[b][kk][ty*8+4];
      ulonglong2 b01 = *(const ulonglong2*)&Ws[b][kk][tx*8];
      ulonglong2 b23 = *(const ulonglong2*)&Ws[b][kk][tx*8+4];
      unsigned long long ad[8];
      ad[0]=dup2(a01.x); ad[1]=dup2(a01.y); ad[2]=dup2(a01.z); ad[3]=dup2(a01.w);
      ad[4]=dup2(a23.x); ad[5]=dup2(a23.y); ad[6]=dup2(a23.z); ad[7]=dup2(a23.w);
      #pragma unroll
      for(int i=0;i<8;i++){
        fma2(acc[i][0], ad[i], b01.x);
        fma2(acc[i][1], ad[i], b01.y);
        fma2(acc[i][2], ad[i], b23.x);
        fma2(acc[i][3], ad[i], b23.y);
      }
    }
    // store chunk c+1 -> buf b^1
    if(c+1 < NC){
      int nb = b^1;
      #pragma unroll
      for(int j=0;j<4;j++){
        As[nb][lk0+j][lr0] = ((const float*)&va0)[j];
        As[nb][lk1+j][lr1] = ((const float*)&va1)[j];
        Ws[nb][lk0+j][lr0] = ((const float*)&vw0)[j];
        Ws[nb][lk1+j][lr1] = ((const float*)&vw1)[j];
      }
      __syncthreads();
    }
  }

  // epilogue
  int j=j0+tx*8;
  float bb[8];
  #pragma unroll
  for(int q=0;q<8;q++){
    float v = bias1 ? bias1[j+q] : 0.f;
    if(bias2) v += bias2[j+q];
    bb[q]=v;
  }
  #pragma unroll
  for(int i=0;i<8;i++){
    int m=m0+ty*8+i;
    float o[8];
    #pragma unroll
    for(int q=0;q<4;q++){
      float lo,hi; unp2(acc[i][q], lo, hi);
      o[q*2]=lo+bb[q*2]; o[q*2+1]=hi+bb[q*2+1];
    }
    if(RELU){
      #pragma unroll
      for(int q=0;q<8;q++) o[q]=fmaxf(o[q],0.f);
    }
    float4 v0; v0.x=o[0]; v0.y=o[1]; v0.z=o[2]; v0.w=o[3];
    float4 v1; v1.x=o[4]; v1.y=o[5]; v1.z=o[6]; v1.w=o[7];
    *(float4*)(C + (size_t)m*OUT + j)     = v0;
    *(float4*)(C + (size_t)m*OUT + j + 4) = v1;
  }
}

// ---------------- graph mean-pool (batch is sorted) ----------------
__global__ void k_gsum(const int* __restrict__ batch){
  int f=threadIdx.x;       // 128
  int n0=blockIdx.x*128;
  int cur=batch[n0];
  float acc=0.f; int rl=0;
  for(int i=0;i<128;i++){
    int n=n0+i;
    int bb=batch[n];
    if(bb!=cur){
      atomicAdd(&g_gsum[cur*HH+f], acc);
      if(f==0) atomicAdd(&g_bcnt[cur], rl);
      acc=0.f; rl=0; cur=bb;
    }
    acc += g_emb[(size_t)n*HH+f];
    rl++;
  }
  atomicAdd(&g_gsum[cur*HH+f], acc);
  if(f==0) atomicAdd(&g_bcnt[cur], rl);
}

// ---------------- LSTM: cluster-of-2, Whh register-resident ----------------
__device__ __forceinline__ float sigf(float v){ return 1.f/(1.f+expf(-v)); }
__device__ __forceinline__ unsigned mapa_u32(unsigned a, unsigned r){
  unsigned o; asm("mapa.shared::cluster.u32 %0, %1, %2;" : "=r"(o) : "r"(a), "r"(r));
  return o;
}
__device__ __forceinline__ void st_cl(unsigned a, float v){
  asm volatile("st.shared::cluster.f32 [%0], %1;" :: "r"(a), "f"(v));
}
#define CLSYNC() do{ asm volatile("barrier.cluster.arrive.aligned;":::"memory"); \
                     asm volatile("barrier.cluster.wait.aligned;":::"memory"); }while(0)

__global__ void __launch_bounds__(256,1) __cluster_dims__(2,1,1)
k_lstm_cl(const float* __restrict__ Whh, const int* __restrict__ plen){
  __shared__ __align__(16) float hs[2][128];
  __shared__ __align__(16) float cs[2][128];
  __shared__ __align__(16) float Gb[2][2][512];  // [buf][row][gatecol]
  __shared__ int lens[2];
  int tid=threadIdx.x;
  unsigned rank; asm("mov.u32 %0, %%cluster_ctarank;" : "=r"(rank));
  int pair = blockIdx.x>>1;
  int r0 = pair*2;
  int gc = rank*256 + tid;      // global gate column 0..511

  if(tid<2) lens[tid]=plen[r0+tid];
  if(tid<256){ hs[0][tid&127]=0.f; cs[0][tid&127]=0.f; }
  if(tid<256){ hs[1][tid&127]=0.f; cs[1][tid&127]=0.f; }

  ulonglong2 w[32];
  const ulonglong2* wr = (const ulonglong2*)(Whh + (size_t)gc*HH);
  #pragma unroll
  for(int q=0;q<32;q++) w[q]=wr[q];

  unsigned gbase = smem_u32(&Gb[0][0][0]);
  unsigned peer = rank^1u;
  __syncthreads();
  CLSYNC();

  int l0=lens[0], l1=lens[1];
  int maxlen = max(l0,l1);
  const float* x0 = g_Xg + ((size_t)r0*LL)*G4 + gc;
  const float* x1 = g_Xg + ((size_t)(r0+1)*LL)*G4 + gc;

  for(int t=0;t<maxlen;t++){
    unsigned long long a0=0ULL, b0=0ULL, a1=0ULL, b1=0ULL;
    #pragma unroll
    for(int q=0;q<32;q+=2){
      ulonglong2 h0a = *(const ulonglong2*)&hs[0][q*4];
      ulonglong2 h0b = *(const ulonglong2*)&hs[0][q*4+4];
      ulonglong2 h1a = *(const ulonglong2*)&hs[1][q*4];
      ulonglong2 h1b = *(const ulonglong2*)&hs[1][q*4+4];
      fma2(a0, w[q].x,   h0a.x); fma2(b0, w[q].y,   h0a.y);
      fma2(a0, w[q+1].x, h0b.x); fma2(b0, w[q+1].y, h0b.y);
      fma2(a1, w[q].x,   h1a.x); fma2(b1, w[q].y,   h1a.y);
      fma2(a1, w[q+1].x, h1b.x); fma2(b1, w[q+1].y, h1b.y);
    }
    float e,oo,e2,o2;
    unp2(a0,e,oo); unp2(b0,e2,o2);
    float g0 = e+oo+e2+o2 + x0[t*G4];
    unp2(a1,e,oo); unp2(b1,e2,o2);
    float g1 = e+oo+e2+o2 + x1[t*G4];

    int buf = t&1;
    Gb[buf][0][gc]=g0; Gb[buf][1][gc]=g1;
    unsigned off0 = gbase + (unsigned)(((buf*2+0)*512 + gc)*4);
    unsigned off1 = gbase + (unsigned)(((buf*2+1)*512 + gc)*4);
    st_cl(mapa_u32(off0, peer), g0);
    st_cl(mapa_u32(off1, peer), g1);
    CLSYNC();

    if(tid<256){
      int rr=tid>>7, k=tid&127;
      if(t < lens[rr]){
        float ig=Gb[buf][rr][k],     fg=Gb[buf][rr][128+k];
        float gg=Gb[buf][rr][256+k], og=Gb[buf][rr][384+k];
        float c = cs[rr][k];
        float cn = sigf(fg)*c + sigf(ig)*tanhf(gg);
        cs[rr][k]=cn;
        hs[rr][k]=sigf(og)*tanhf(cn);
      }
    }
    __syncthreads();
  }
  if(tid<256){
    int rr=tid>>7, k=tid&127;
    g_hst[(size_t)(r0+rr)*HH + k] = hs[rr][k];
  }
  CLSYNC();
}

// ---------------- final: flow MLP + concat + scoring MLP ----------------
__global__ void k_combine(const float* __restrict__ flow, const float* __restrict__ Wf,
   const float* __restrict__ bf, const float* __restrict__ Ws1, const float* __restrict__ bs1,
   const float* __restrict__ Ws2, const float* __restrict__ bs2, float* __restrict__ out)
{
  __shared__ __align__(16) float comb[320];
  __shared__ float red[128];
  int b=blockIdx.x, tid=threadIdx.x;   // 128 threads
  float cnt=(float)max(g_bcnt[b],1);
  comb[tid]      = g_gsum[b*HH+tid]/cnt;
  comb[128+tid]  = g_hst[b*HH+tid];
  if(tid<64){
    float a=bf[tid];
    #pragma unroll
    for(int i=0;i<16;i++) a += flow[b*FF+i]*Wf[tid*FF+i];
    comb[256+tid]=fmaxf(a,0.f);
  }
  __syncthreads();
  float s=bs1[tid];
  const float4* w4=(const float4*)(Ws1 + (size_t)tid*320);
  const float4* c4=(const float4*)comb;
  #pragma unroll 8
  for(int k=0;k<80;k++){
    float4 w=w4[k], c=c4[k];
    s += w.x*c.x + w.y*c.y + w.z*c.z + w.w*c.w;
  }
  s=fmaxf(s,0.f);
  red[tid]=s*Ws2[tid];
  __syncthreads();
  for(int o=64;o>0;o>>=1){ if(tid<o) red[tid]+=red[tid+o]; __syncthreads(); }
  if(tid==0) out[b]=red[0]+bs2[0];
}

// ---------------- launch ----------------
extern "C" void kernel_launch(void* const* d_in, const int* in_sizes, int n_in,
                              void* d_out, int out_size){
  const float* x   =(const float*)d_in[0];
  const int*   ei  =(const int*)  d_in[1];
  const int*   batch=(const int*) d_in[2];
  const int*   pidx=(const int*)  d_in[3];
  const int*   plen=(const int*)  d_in[4];
  const float* flow=(const float*)d_in[5];
  const float* Wl1=(const float*)d_in[6];
  const float* Wr1=(const float*)d_in[7];
  const float* b1 =(const float*)d_in[8];
  const float* Wl2=(const float*)d_in[9];
  const float* Wr2=(const float*)d_in[10];
  const float* b2 =(const float*)d_in[11];
  const float* Wih=(const float*)d_in[12];
  const float* Whh=(const float*)d_in[13];
  const float* bih=(const float*)d_in[14];
  const float* bhh=(const float*)d_in[15];
  const float* Wf =(const float*)d_in[16];
  const float* bf =(const float*)d_in[17];
  const float* Ws1=(const float*)d_in[18];
  const float* bs1=(const float*)d_in[19];
  const float* Ws2=(const float*)d_in[20];
  const float* bs2=(const float*)d_in[21];
  float* out=(float*)d_out;

  float *p_mean,*p_h1,*p_emb,*p_xg;
  cudaGetSymbolAddress((void**)&p_mean, g_mean);
  cudaGetSymbolAddress((void**)&p_h1,   g_h1);
  cudaGetSymbolAddress((void**)&p_emb,  g_emb);
  cudaGetSymbolAddress((void**)&p_xg,   g_Xg);

  k_zero<<<NN/256,256>>>();
  k_degree<<<EE/256,256>>>(ei);
  k_scanA<<<128,256>>>();
  k_scanB<<<1,128>>>();
  k_scanC<<<128,256>>>();
  k_csr<<<EE/256,256>>>(ei);

  // SAGE layer 1: h1 = relu(mean@Wl1^T + b1 + x@Wr1^T)
  k_agg1<<<NN/8,256>>>(x);
  k_gemm_f2<true,false><<<dim3(NN/128,1),256>>>(p_mean,FN, x,FN, Wl1,Wr1, b1,nullptr, nullptr, p_h1, HH);

  // SAGE layer 2
  k_agg2<<<NN/8,256>>>();
  k_gemm_f2<true,false><<<dim3(NN/128,1),256>>>(p_mean,HH, p_h1,HH, Wl2,Wr2, b2,nullptr, nullptr, p_emb, HH);

  // graph pooling
  k_gsum<<<NN/128,128>>>(batch);

  // LSTM input precompute: Xg[b,t,:] = node_emb[path_idx] @ Wih^T + bih + bhh
  k_gemm_f2<false,true><<<dim3(BB*LL/128,4),256>>>(p_emb,HH, nullptr,0, Wih,nullptr, bih,bhh, pidx, p_xg, G4);

  // LSTM recurrence (cluster kernel, Whh in registers)
  k_lstm_cl<<<BB,256>>>(Whh, plen);

  // final scoring
  k_combine<<<BB,128>>>(flow,Wf,bf,Ws1,bs1,Ws2,bs2,out);
}

// round 9
// speedup vs baseline: 1.7179x; 1.0369x over previous
#include <cuda_runtime.h>
#include <cuda_fp16.h>
#include <math.h>

#define NN 131072
#define FN 64
#define FF 16
#define HH 128
#define EE 2097152
#define BB 256
#define LL 32
#define G4 512

// ---------------- scratch (device globals; no allocation) ----------------
__device__ int    g_deg[NN];
__device__ int    g_off[NN];
__device__ int    g_cur[NN];
__device__ int    g_bsum[128];
__device__ int    g_csr[EE];
__device__ float  g_mean[NN*HH];     // layer1 uses stride 64, layer2 stride 128
__device__ __half g_xh[NN*FN];       // x in fp16 (agg1 gather source)
__device__ __half g_h1h[NN*HH];      // h1 in fp16 (agg2 gather + gemm2 A2)
__device__ float  g_emb[NN*HH];
__device__ float  g_gsum[BB*HH];
__device__ int    g_bcnt[BB];
__device__ float  g_Xg[BB*LL*G4];
__device__ float  g_hst[BB*HH];

// ---------------- f32x2 packed helpers ----------------
__device__ __forceinline__ void fma2(unsigned long long &d, unsigned long long a, unsigned long long b){
  asm("fma.rn.f32x2 %0, %1, %2, %0;" : "+l"(d) : "l"(a), "l"(b));
}
__device__ __forceinline__ unsigned long long dup2(float a){
  unsigned long long r; asm("mov.b64 %0, {%1, %1};" : "=l"(r) : "f"(a)); return r;
}
__device__ __forceinline__ void unp2(unsigned long long v, float &lo, float &hi){
  asm("mov.b64 {%0, %1}, %2;" : "=f"(lo), "=f"(hi) : "l"(v));
}
__device__ __forceinline__ unsigned smem_u32(const void* p){
  unsigned a; asm("{ .reg .u64 t; cvta.to.shared.u64 t, %1; cvt.u32.u64 %0, t; }" : "=r"(a) : "l"(p));
  return a;
}

// ---------------- init ----------------
__global__ void k_zero(){
  int i = blockIdx.x*256 + threadIdx.x;
  if (i < NN) g_deg[i] = 0;
  if (i < BB) g_bcnt[i] = 0;
  if (i < BB*HH) g_gsum[i]=0.f;
}

// x -> half (8.4M elems, 4 per thread)
__global__ void k_x2h(const float* __restrict__ x){
  int i = blockIdx.x*256 + threadIdx.x;
  float4 v = *(const float4*)(x + (size_t)i*4);
  __half2 a = __floats2half2_rn(v.x, v.y);
  __half2 b = __floats2half2_rn(v.z, v.w);
  uint2 u; u.x = *(unsigned*)&a; u.y = *(unsigned*)&b;
  *(uint2*)(g_xh + (size_t)i*4) = u;
}

// ---------------- CSR build ----------------
__global__ void k_degree(const int* __restrict__ ei){
  int e = blockIdx.x*256+threadIdx.x;
  if (e < EE) atomicAdd(&g_deg[ei[EE+e]], 1);
}

__global__ void k_scanA(){
  __shared__ int s[256];
  int tid=threadIdx.x;
  int base = blockIdx.x*1024 + tid*4;
  int t = g_deg[base]+g_deg[base+1]+g_deg[base+2]+g_deg[base+3];
  s[tid]=t; __syncthreads();
  for(int o=128;o>0;o>>=1){ if(tid<o) s[tid]+=s[tid+o]; __syncthreads(); }
  if(tid==0) g_bsum[blockIdx.x]=s[0];
}

__global__ void k_scanB(){
  __shared__ int s[128];
  int t=threadIdx.x;
  int v=g_bsum[t]; s[t]=v; __syncthreads();
  for(int o=1;o<128;o<<=1){
    int a = (t>=o)? s[t-o] : 0; __syncthreads();
    s[t]+=a; __syncthreads();
  }
  g_bsum[t]=s[t]-v;   // exclusive block base
}

__global__ void k_scanC(){
  __shared__ int s[256];
  int tid=threadIdx.x;
  int base = blockIdx.x*1024 + tid*4;
  int d0=g_deg[base],d1=g_deg[base+1],d2=g_deg[base+2],d3=g_deg[base+3];
  int tot=d0+d1+d2+d3;
  s[tid]=tot; __syncthreads();
  for(int o=1;o<256;o<<=1){
    int a=(tid>=o)? s[tid-o]:0; __syncthreads();
    s[tid]+=a; __syncthreads();
  }
  int run = g_bsum[blockIdx.x] + s[tid]-tot;
  g_off[base  ]=run; g_cur[base  ]=run; run+=d0;
  g_off[base+1]=run; g_cur[base+1]=run; run+=d1;
  g_off[base+2]=run; g_cur[base+2]=run; run+=d2;
  g_off[base+3]=run; g_cur[base+3]=run;
}

__global__ void k_csr(const int* __restrict__ ei){
  int e = blockIdx.x*256+threadIdx.x;
  if (e < EE){
    int src = ei[e], dst = ei[EE+e];
    int p = atomicAdd(&g_cur[dst],1);
    g_csr[p]=src;
  }
}

// ---------------- neighbor-mean gathers (warp per node, fp16 sources) ----------------
__global__ void k_agg1(){
  int w = (blockIdx.x*256+threadIdx.x)>>5;
  int lane = threadIdx.x&31;
  if (w>=NN) return;
  int beg=g_off[w], d=g_deg[w];
  float ax=0.f, ay=0.f;
  for(int i=0;i<d;i++){
    int src=g_csr[beg+i];
    __half2 h = *(const __half2*)(g_xh + (size_t)src*FN + lane*2);
    float2 v = __half22float2(h);
    ax+=v.x; ay+=v.y;
  }
  float inv = 1.0f/(float)max(d,1);
  float2 o; o.x=ax*inv; o.y=ay*inv;
  *(float2*)(g_mean + (size_t)w*FN + lane*2) = o;
}

__global__ void k_agg2(){
  int w = (blockIdx.x*256+threadIdx.x)>>5;
  int lane=threadIdx.x&31;
  if (w>=NN) return;
  int beg=g_off[w], d=g_deg[w];
  float4 acc = {0.f,0.f,0.f,0.f};
  for(int i=0;i<d;i++){
    int src=g_csr[beg+i];
    uint2 u = *(const uint2*)(g_h1h + (size_t)src*HH + lane*4);
    float2 v0 = __half22float2(*(__half2*)&u.x);
    float2 v1 = __half22float2(*(__half2*)&u.y);
    acc.x+=v0.x; acc.y+=v0.y; acc.z+=v1.x; acc.w+=v1.y;
  }
  float inv=1.f/(float)max(d,1);
  acc.x*=inv; acc.y*=inv; acc.z*=inv; acc.w*=inv;
  *(float4*)(g_mean + (size_t)w*HH + lane*4) = acc;
}

// ---------------- f32x2 SGEMM, double-buffered, transposed smem ----------------
// C = act([A1|A2] @ [W1|W2]^T + bias1 + bias2)
// BM=128, BN=128, BK=16, 256 threads, 8x8 microtile as 8x4 f32x2 pairs.
// A2H: A2 is fp16. OUTH: output written as fp16.
template<bool RELU, bool GATHER, bool A2H, bool OUTH>
__global__ void __launch_bounds__(256,2) k_gemm_f2(
    const float* __restrict__ A1, int K1,
    const void* __restrict__ A2v, int K2,
    const float* __restrict__ W1, const float* __restrict__ W2,
    const float* __restrict__ bias1, const float* __restrict__ bias2,
    const int* __restrict__ gidx,
    void* __restrict__ Cv, int OUT)
{
  __shared__ __align__(16) float As[2][16][136];
  __shared__ __align__(16) float Ws[2][16][136];
  int tid=threadIdx.x;
  int m0=blockIdx.x*128, j0=blockIdx.y*128;
  int ty=tid>>4, tx=tid&15;
  unsigned long long acc[8][4];
  #pragma unroll
  for(int i=0;i<8;i++)
    #pragma unroll
    for(int q=0;q<4;q++) acc[i][q]=0ULL;

  int lr0 = tid>>2,        lk0 = (tid&3)*4;
  int lr1 = (tid+256)>>2,  lk1 = (tid&3)*4;
  int arow0 = GATHER ? __ldg(&gidx[m0+lr0]) : (m0+lr0);
  int arow1 = GATHER ? __ldg(&gidx[m0+lr1]) : (m0+lr1);

  int NC1 = K1/16, NC = (K1+K2)/16;

  float4 va0,va1,vw0,vw1;
  {
    va0 = *(const float4*)(A1 + (size_t)arow0*K1 + lk0);
    va1 = *(const float4*)(A1 + (size_t)arow1*K1 + lk1);
    vw0 = *(const float4*)(W1 + (size_t)(j0+lr0)*K1 + lk0);
    vw1 = *(const float4*)(W1 + (size_t)(j0+lr1)*K1 + lk1);
  }
  #pragma unroll
  for(int j=0;j<4;j++){
    As[0][lk0+j][lr0] = ((const float*)&va0)[j];
    As[0][lk1+j][lr1] = ((const float*)&va1)[j];
    Ws[0][lk0+j][lr0] = ((const float*)&vw0)[j];
    Ws[0][lk1+j][lr1] = ((const float*)&vw1)[j];
  }
  __syncthreads();

  for(int c=0;c<NC;c++){
    int b = c&1;
    if(c+1 < NC){
      bool in1 = (c+1 < NC1);
      if(in1){
        int koff = (c+1)*16;
        va0 = *(const float4*)(A1 + (size_t)arow0*K1 + koff + lk0);
        va1 = *(const float4*)(A1 + (size_t)arow1*K1 + koff + lk1);
        vw0 = *(const float4*)(W1 + (size_t)(j0+lr0)*K1 + koff + lk0);
        vw1 = *(const float4*)(W1 + (size_t)(j0+lr1)*K1 + koff + lk1);
      } else {
        int koff = (c+1-NC1)*16;
        if(A2H){
          const __half* A2 = (const __half*)A2v;
          uint2 u0 = *(const uint2*)(A2 + (size_t)arow0*K2 + koff + lk0);
          uint2 u1 = *(const uint2*)(A2 + (size_t)arow1*K2 + koff + lk1);
          float2 p0=__half22float2(*(__half2*)&u0.x), p1=__half22float2(*(__half2*)&u0.y);
          va0 = make_float4(p0.x,p0.y,p1.x,p1.y);
          float2 q0=__half22float2(*(__half2*)&u1.x), q1=__half22float2(*(__half2*)&u1.y);
          va1 = make_float4(q0.x,q0.y,q1.x,q1.y);
        } else {
          const float* A2 = (const float*)A2v;
          va0 = *(const float4*)(A2 + (size_t)arow0*K2 + koff + lk0);
          va1 = *(const float4*)(A2 + (size_t)arow1*K2 + koff + lk1);
        }
        vw0 = *(const float4*)(W2 + (size_t)(j0+lr0)*K2 + koff + lk0);
        vw1 = *(const float4*)(W2 + (size_t)(j0+lr1)*K2 + koff + lk1);
      }
    }
    #pragma unroll
    for(int kk=0;kk<16;kk++){
      float4 a01 = *(const float4*)&As[b][kk][ty*8];
      float4 a23 = *(const float4*)&As[b][kk][ty*8+4];
      ulonglong2 b01 = *(const ulonglong2*)&Ws[b][kk][tx*8];
      ulonglong2 b23 = *(const ulonglong2*)&Ws[b][kk][tx*8+4];
      unsigned long long ad[8];
      ad[0]=dup2(a01.x); ad[1]=dup2(a01.y); ad[2]=dup2(a01.z); ad[3]=dup2(a01.w);
      ad[4]=dup2(a23.x); ad[5]=dup2(a23.y); ad[6]=dup2(a23.z); ad[7]=dup2(a23.w);
      #pragma unroll
      for(int i=0;i<8;i++){
        fma2(acc[i][0], ad[i], b01.x);
        fma2(acc[i][1], ad[i], b01.y);
        fma2(acc[i][2], ad[i], b23.x);
        fma2(acc[i][3], ad[i], b23.y);
      }
    }
    if(c+1 < NC){
      int nb = b^1;
      #pragma unroll
      for(int j=0;j<4;j++){
        As[nb][lk0+j][lr0] = ((const float*)&va0)[j];
        As[nb][lk1+j][lr1] = ((const float*)&va1)[j];
        Ws[nb][lk0+j][lr0] = ((const float*)&vw0)[j];
        Ws[nb][lk1+j][lr1] = ((const float*)&vw1)[j];
      }
      __syncthreads();
    }
  }

  // epilogue
  int j=j0+tx*8;
  float bb[8];
  #pragma unroll
  for(int q=0;q<8;q++){
    float v = bias1 ? bias1[j+q] : 0.f;
    if(bias2) v += bias2[j+q];
    bb[q]=v;
  }
  #pragma unroll
  for(int i=0;i<8;i++){
    int m=m0+ty*8+i;
    float o[8];
    #pragma unroll
    for(int q=0;q<4;q++){
      float lo,hi; unp2(acc[i][q], lo, hi);
      o[q*2]=lo+bb[q*2]; o[q*2+1]=hi+bb[q*2+1];
    }
    if(RELU){
      #pragma unroll
      for(int q=0;q<8;q++) o[q]=fmaxf(o[q],0.f);
    }
    if(OUTH){
      __half* Ch = (__half*)Cv;
      __half2 h0=__floats2half2_rn(o[0],o[1]), h1=__floats2half2_rn(o[2],o[3]);
      __half2 h2=__floats2half2_rn(o[4],o[5]), h3=__floats2half2_rn(o[6],o[7]);
      uint4 u; u.x=*(unsigned*)&h0; u.y=*(unsigned*)&h1; u.z=*(unsigned*)&h2; u.w=*(unsigned*)&h3;
      *(uint4*)(Ch + (size_t)m*OUT + j) = u;
    } else {
      float* C = (float*)Cv;
      float4 v0; v0.x=o[0]; v0.y=o[1]; v0.z=o[2]; v0.w=o[3];
      float4 v1; v1.x=o[4]; v1.y=o[5]; v1.z=o[6]; v1.w=o[7];
      *(float4*)(C + (size_t)m*OUT + j)     = v0;
      *(float4*)(C + (size_t)m*OUT + j + 4) = v1;
    }
  }
}

// ---------------- graph mean-pool (batch is sorted) ----------------
__global__ void k_gsum(const int* __restrict__ batch){
  int f=threadIdx.x;       // 128
  int n0=blockIdx.x*128;
  int cur=batch[n0];
  float acc=0.f; int rl=0;
  for(int i=0;i<128;i++){
    int n=n0+i;
    int bb=batch[n];
    if(bb!=cur){
      atomicAdd(&g_gsum[cur*HH+f], acc);
      if(f==0) atomicAdd(&g_bcnt[cur], rl);
      acc=0.f; rl=0; cur=bb;
    }
    acc += g_emb[(size_t)n*HH+f];
    rl++;
  }
  atomicAdd(&g_gsum[cur*HH+f], acc);
  if(f==0) atomicAdd(&g_bcnt[cur], rl);
}

// ---------------- LSTM: cluster-of-2, Whh register-resident ----------------
__device__ __forceinline__ float sigf(float v){ return 1.f/(1.f+expf(-v)); }
__device__ __forceinline__ unsigned mapa_u32(unsigned a, unsigned r){
  unsigned o; asm("mapa.shared::cluster.u32 %0, %1, %2;" : "=r"(o) : "r"(a), "r"(r));
  return o;
}
__device__ __forceinline__ void st_cl(unsigned a, float v){
  asm volatile("st.shared::cluster.f32 [%0], %1;" :: "r"(a), "f"(v));
}
#define CLSYNC() do{ asm volatile("barrier.cluster.arrive.aligned;":::"memory"); \
                     asm volatile("barrier.cluster.wait.aligned;":::"memory"); }while(0)

__global__ void __launch_bounds__(256,1) __cluster_dims__(2,1,1)
k_lstm_cl(const float* __restrict__ Whh, const int* __restrict__ plen){
  __shared__ __align__(16) float hs[2][128];
  __shared__ __align__(16) float cs[2][128];
  __shared__ __align__(16) float Gb[2][2][512];  // [buf][row][gatecol]
  __shared__ int lens[2];
  int tid=threadIdx.x;
  unsigned rank; asm("mov.u32 %0, %%cluster_ctarank;" : "=r"(rank));
  int pair = blockIdx.x>>1;
  int r0 = pair*2;
  int gc = rank*256 + tid;      // global gate column 0..511

  if(tid<2) lens[tid]=plen[r0+tid];
  if(tid<256){ hs[0][tid&127]=0.f; cs[0][tid&127]=0.f; }
  if(tid<256){ hs[1][tid&127]=0.f; cs[1][tid&127]=0.f; }

  ulonglong2 w[32];
  const ulonglong2* wr = (const ulonglong2*)(Whh + (size_t)gc*HH);
  #pragma unroll
  for(int q=0;q<32;q++) w[q]=wr[q];

  unsigned gbase = smem_u32(&Gb[0][0][0]);
  unsigned peer = rank^1u;
  __syncthreads();
  CLSYNC();

  int l0=lens[0], l1=lens[1];
  int maxlen = max(l0,l1);
  const float* x0 = g_Xg + ((size_t)r0*LL)*G4 + gc;
  const float* x1 = g_Xg + ((size_t)(r0+1)*LL)*G4 + gc;

  for(int t=0;t<maxlen;t++){
    unsigned long long a0=0ULL, b0=0ULL, a1=0ULL, b1=0ULL;
    #pragma unroll
    for(int q=0;q<32;q+=2){
      ulonglong2 h0a = *(const ulonglong2*)&hs[0][q*4];
      ulonglong2 h0b = *(const ulonglong2*)&hs[0][q*4+4];
      ulonglong2 h1a = *(const ulonglong2*)&hs[1][q*4];
      ulonglong2 h1b = *(const ulonglong2*)&hs[1][q*4+4];
      fma2(a0, w[q].x,   h0a.x); fma2(b0, w[q].y,   h0a.y);
      fma2(a0, w[q+1].x, h0b.x); fma2(b0, w[q+1].y, h0b.y);
      fma2(a1, w[q].x,   h1a.x); fma2(b1, w[q].y,   h1a.y);
      fma2(a1, w[q+1].x, h1b.x); fma2(b1, w[q+1].y, h1b.y);
    }
    float e,oo,e2,o2;
    unp2(a0,e,oo); unp2(b0,e2,o2);
    float g0 = e+oo+e2+o2 + x0[t*G4];
    unp2(a1,e,oo); unp2(b1,e2,o2);
    float g1 = e+oo+e2+o2 + x1[t*G4];

    int buf = t&1;
    Gb[buf][0][gc]=g0; Gb[buf][1][gc]=g1;
    unsigned off0 = gbase + (unsigned)(((buf*2+0)*512 + gc)*4);
    unsigned off1 = gbase + (unsigned)(((buf*2+1)*512 + gc)*4);
    st_cl(mapa_u32(off0, peer), g0);
    st_cl(mapa_u32(off1, peer), g1);
    CLSYNC();

    if(tid<256){
      int rr=tid>>7, k=tid&127;
      if(t < lens[rr]){
        float ig=Gb[buf][rr][k],     fg=Gb[buf][rr][128+k];
        float gg=Gb[buf][rr][256+k], og=Gb[buf][rr][384+k];
        float c = cs[rr][k];
        float cn = sigf(fg)*c + sigf(ig)*tanhf(gg);
        cs[rr][k]=cn;
        hs[rr][k]=sigf(og)*tanhf(cn);
      }
    }
    __syncthreads();
  }
  if(tid<256){
    int rr=tid>>7, k=tid&127;
    g_hst[(size_t)(r0+rr)*HH + k] = hs[rr][k];
  }
  CLSYNC();
}

// ---------------- final: flow MLP + concat + scoring MLP ----------------
__global__ void k_combine(const float* __restrict__ flow, const float* __restrict__ Wf,
   const float* __restrict__ bf, const float* __restrict__ Ws1, const float* __restrict__ bs1,
   const float* __restrict__ Ws2, const float* __restrict__ bs2, float* __restrict__ out)
{
  __shared__ __align__(16) float comb[320];
  __shared__ float red[128];
  int b=blockIdx.x, tid=threadIdx.x;   // 128 threads
  float cnt=(float)max(g_bcnt[b],1);
  comb[tid]      = g_gsum[b*HH+tid]/cnt;
  comb[128+tid]  = g_hst[b*HH+tid];
  if(tid<64){
    float a=bf[tid];
    #pragma unroll
    for(int i=0;i<16;i++) a += flow[b*FF+i]*Wf[tid*FF+i];
    comb[256+tid]=fmaxf(a,0.f);
  }
  __syncthreads();
  float s=bs1[tid];
  const float4* w4=(const float4*)(Ws1 + (size_t)tid*320);
  const float4* c4=(const float4*)comb;
  #pragma unroll 8
  for(int k=0;k<80;k++){
    float4 w=w4[k], c=c4[k];
    s += w.x*c.x + w.y*c.y + w.z*c.z + w.w*c.w;
  }
  s=fmaxf(s,0.f);
  red[tid]=s*Ws2[tid];
  __syncthreads();
  for(int o=64;o>0;o>>=1){ if(tid<o) red[tid]+=red[tid+o]; __syncthreads(); }
  if(tid==0) out[b]=red[0]+bs2[0];
}

// ---------------- launch ----------------
extern "C" void kernel_launch(void* const* d_in, const int* in_sizes, int n_in,
                              void* d_out, int out_size){
  const float* x   =(const float*)d_in[0];
  const int*   ei  =(const int*)  d_in[1];
  const int*   batch=(const int*) d_in[2];
  const int*   pidx=(const int*)  d_in[3];
  const int*   plen=(const int*)  d_in[4];
  const float* flow=(const float*)d_in[5];
  const float* Wl1=(const float*)d_in[6];
  const float* Wr1=(const float*)d_in[7];
  const float* b1 =(const float*)d_in[8];
  const float* Wl2=(const float*)d_in[9];
  const float* Wr2=(const float*)d_in[10];
  const float* b2 =(const float*)d_in[11];
  const float* Wih=(const float*)d_in[12];
  const float* Whh=(const float*)d_in[13];
  const float* bih=(const float*)d_in[14];
  const float* bhh=(const float*)d_in[15];
  const float* Wf =(const float*)d_in[16];
  const float* bf =(const float*)d_in[17];
  const float* Ws1=(const float*)d_in[18];
  const float* bs1=(const float*)d_in[19];
  const float* Ws2=(const float*)d_in[20];
  const float* bs2=(const float*)d_in[21];
  float* out=(float*)d_out;

  float *p_mean,*p_emb,*p_xg;
  __half *p_h1h;
  cudaGetSymbolAddress((void**)&p_mean, g_mean);
  cudaGetSymbolAddress((void**)&p_h1h,  g_h1h);
  cudaGetSymbolAddress((void**)&p_emb,  g_emb);
  cudaGetSymbolAddress((void**)&p_xg,   g_Xg);

  k_zero<<<NN/256,256>>>();
  k_x2h<<<NN*FN/4/256,256>>>(x);
  k_degree<<<EE/256,256>>>(ei);
  k_scanA<<<128,256>>>();
  k_scanB<<<1,128>>>();
  k_scanC<<<128,256>>>();
  k_csr<<<EE/256,256>>>(ei);

  // SAGE layer 1: h1 = relu(mean@Wl1^T + b1 + x@Wr1^T) -> fp16
  k_agg1<<<NN/8,256>>>();
  k_gemm_f2<true,false,false,true><<<dim3(NN/128,1),256>>>(
      p_mean,FN, x,FN, Wl1,Wr1, b1,nullptr, nullptr, p_h1h, HH);

  // SAGE layer 2: emb = relu(mean2@Wl2^T + b2 + h1@Wr2^T), h1 read as fp16
  k_agg2<<<NN/8,256>>>();
  k_gemm_f2<true,false,true,false><<<dim3(NN/128,1),256>>>(
      p_mean,HH, p_h1h,HH, Wl2,Wr2, b2,nullptr, nullptr, p_emb, HH);

  // graph pooling
  k_gsum<<<NN/128,128>>>(batch);

  // LSTM input precompute: Xg[b,t,:] = node_emb[path_idx] @ Wih^T + bih + bhh
  k_gemm_f2<false,true,false,false><<<dim3(BB*LL/128,4),256>>>(
      p_emb,HH, nullptr,0, Wih,nullptr, bih,bhh, pidx, p_xg, G4);

  // LSTM recurrence (cluster kernel, Whh in registers)
  k_lstm_cl<<<BB,256>>>(Whh, plen);

  // final scoring
  k_combine<<<BB,128>>>(flow,Wf,bf,Ws1,bs1,Ws2,bs2,out);
}